// round 14
// baseline (speedup 1.0000x reference)
#include <cuda_runtime.h>

#define NN 512
#define CC 16
#define LTL 3
#define AGG_IN 1028
#define EPC 64             // edges per CTA
#define TPB 64
#define NCHUNK 8           // chunks per q
#define PF_AHEAD 1280      // same-layer prefetch distance (~1 wave of CTAs)

// scratch (no allocation allowed)
__device__ float g_part[NN * 3 * NCHUNK];  // per-(q,k,chunk) aggregator partials
__device__ unsigned g_cnt[NN];             // arrival counters (self-resetting)
__device__ float g_act[2][NN];             // ping-pong activations

__device__ __forceinline__ float tanh_e(float x) {
    x = fminf(fmaxf(x, -15.0f), 15.0f);
    float e = __expf(2.0f * x);
    return __fdividef(e - 1.0f, e + 1.0f);
}

__device__ __forceinline__ void cp_async16(void* smem_dst, const void* gsrc) {
    unsigned s = (unsigned)__cvta_generic_to_shared(smem_dst);
    asm volatile("cp.async.cg.shared.global [%0], [%1], 16;\n" :: "r"(s), "l"(gsrc));
}

__device__ __forceinline__ void pf_l2(const void* g) {
    asm volatile("prefetch.global.L2 [%0];\n" :: "l"(g));
}

// ---------------------------------------------------------------------------
// Edge kernel (R13 architecture: 64 edges/CTA, split-commit overlap, fused
// epilogue, register diet) + SAME-LAYER distance prefetch:
// each CTA L2-prefetches the weight region of CTA bid+PF_AHEAD, so by the time
// that CTA runs, its cp.asyncs are L2 hits (~250cyc) instead of DRAM (~600cyc).
// Decouples the DRAM fetch stream from every CTA's critical path.
// ---------------------------------------------------------------------------
__global__ __launch_bounds__(TPB, 16) void edge_kernel(
    const float* __restrict__ a_ext, int in_buf, int out_buf, int l,
    float* __restrict__ dout,
    const float* __restrict__ vW,  const float* __restrict__ vb,
    const float* __restrict__ sW1, const float* __restrict__ sb1,
    const float* __restrict__ sW2, const float* __restrict__ sb2,
    const float* __restrict__ aW1, const float* __restrict__ ab1,
    const float* __restrict__ aW2, const float* __restrict__ ab2)
{
    __shared__ float4 svW[EPC * 5];    // padded: 5 granules per edge (4 used)
    __shared__ float4 svb[EPC * 5];
    __shared__ float4 sw1[EPC * 13];   // padded: 13 granules per edge (12 used)
    __shared__ float red[3][2];

    const int t   = threadIdx.x;
    const int cta = blockIdx.x;
    const size_t e0 = (size_t)cta * EPC;
    const int q     = cta >> 3;
    const int chunk = cta & 7;
    const int p     = (chunk << 6) + t;
    const size_t eg = e0 + t;

    // --- group A: vW + vb (needed first, by the VEC phase) ---
    const float4* gvW = (const float4*)(vW  + e0 * CC);
    const float4* gvb = (const float4*)(vb  + e0 * CC);
    #pragma unroll
    for (int r = 0; r < 4; ++r) {
        int i = t + r * TPB;
        cp_async16(&svW[(i >> 2) * 5 + (i & 3)], &gvW[i]);
    }
    #pragma unroll
    for (int r = 0; r < 4; ++r) {
        int i = t + r * TPB;
        cp_async16(&svb[(i >> 2) * 5 + (i & 3)], &gvb[i]);
    }
    asm volatile("cp.async.commit_group;\n" ::: "memory");

    // --- group B: sW1 (needed later, by the synapse phase) ---
    const float4* gs1 = (const float4*)(sW1 + e0 * 48);
    #pragma unroll
    for (int r = 0; r < 12; ++r) {
        int i = t + r * TPB;
        int e = i / 12;
        cp_async16(&sw1[e * 13 + (i - e * 12)], &gs1[i]);
    }
    asm volatile("cp.async.commit_group;\n" ::: "memory");

    // --- SAME-LAYER distance prefetch for CTA bid+PF_AHEAD (fire-and-forget,
    //     no regs/smem; makes that CTA's cp.asyncs L2 hits) ---
    {
        const int pfb = cta + PF_AHEAD;
        if (pfb < (NN * NN) / EPC) {
            const size_t pe0 = (size_t)pfb * EPC;
            const char* nW = (const char*)(vW  + pe0 * CC);   // 4 KB = 32 lines
            const char* nB = (const char*)(vb  + pe0 * CC);   // 4 KB = 32 lines
            const char* n1 = (const char*)(sW1 + pe0 * 48);   // 12 KB = 96 lines
            if (t < 32) { pf_l2(nW + t * 128); pf_l2(nB + t * 128); }
            pf_l2(n1 + t * 128);                 // lines 0..63
            if (t < 32) pf_l2(n1 + (64 + t) * 128);   // lines 64..95
            else {
                // small arrays of CTA pfb: sb1 (6 lines), sW2 (6), sb2 (2)
                int u = t - 32;
                if (u < 6)       pf_l2((const char*)(sb1 + pe0 * 3) + u * 128);
                else if (u < 12) pf_l2((const char*)(sW2 + pe0 * 3) + (u - 6) * 128);
                else if (u < 14) pf_l2((const char*)(sb2 + pe0) + (u - 12) * 128);
                else if (u < 20) {
                    // aW1 row segments for (q,k) of CTA pfb: 2 lines per k
                    int k = (u - 14) >> 1, half = (u - 14) & 1;
                    const int pq = pfb >> 3, pp = (pfb & 7) << 6;
                    const char* ar = (const char*)(aW1 + ((size_t)pq * 3 + k) * AGG_IN + pp);
                    pf_l2(ar + half * 128);
                }
            }
        }
    }

    // --- small direct loads (overlap with both async groups) ---
    const float* a_in = a_ext ? a_ext : g_act[in_buf];
    const float ap = __ldg(&a_in[p]);
    const float b1_0 = __ldg(&sb1[eg * 3 + 0]);
    const float b1_1 = __ldg(&sb1[eg * 3 + 1]);
    const float b1_2 = __ldg(&sb1[eg * 3 + 2]);
    const float w2_0 = __ldg(&sW2[eg * 3 + 0]);
    const float w2_1 = __ldg(&sW2[eg * 3 + 1]);
    const float w2_2 = __ldg(&sW2[eg * 3 + 2]);
    const float b2   = __ldg(&sb2[eg]);
    float aw[3];
    #pragma unroll
    for (int k = 0; k < 3; ++k)
        aw[k] = __ldg(&aW1[((size_t)q * 3 + k) * AGG_IN + p]);

    // --- wait for group A only; B (sW1) still streaming ---
    asm volatile("cp.async.wait_group 1;\n" ::: "memory");
    __syncthreads();

    // --- VEC: f[c] = tanh(ap*vW[c] + vb[c]) --- (overlaps sW1 fetch)
    float f[16];
    #pragma unroll
    for (int g = 0; g < 4; ++g) {
        float4 w = svW[t * 5 + g];
        float4 b = svb[t * 5 + g];
        f[4*g+0] = tanh_e(fmaf(ap, w.x, b.x));
        f[4*g+1] = tanh_e(fmaf(ap, w.y, b.y));
        f[4*g+2] = tanh_e(fmaf(ap, w.z, b.z));
        f[4*g+3] = tanh_e(fmaf(ap, w.w, b.w));
    }

    // --- now require sW1 ---
    asm volatile("cp.async.wait_group 0;\n" ::: "memory");
    __syncthreads();

    // --- Synapse: Linear(16->3) -> tanh -> Linear(3->1) -> tanh ---
    float h1[3];
    const float bb1[3] = {b1_0, b1_1, b1_2};
    #pragma unroll
    for (int o = 0; o < 3; ++o) {
        float acc = bb1[o];
        #pragma unroll
        for (int g = 0; g < 4; ++g) {
            float4 w = sw1[t * 13 + o * 4 + g];
            acc = fmaf(w.x, f[4*g+0], acc);
            acc = fmaf(w.y, f[4*g+1], acc);
            acc = fmaf(w.z, f[4*g+2], acc);
            acc = fmaf(w.w, f[4*g+3], acc);
        }
        h1[o] = tanh_e(acc);
    }
    float sv = b2;
    sv = fmaf(w2_0, h1[0], sv);
    sv = fmaf(w2_1, h1[1], sv);
    sv = fmaf(w2_2, h1[2], sv);
    const float s = tanh_e(sv);

    // --- fused aggregator partials: sum_p aW1[q,k,p]*s_p over this chunk ---
    float pk[3] = {aw[0] * s, aw[1] * s, aw[2] * s};
    #pragma unroll
    for (int off = 16; off > 0; off >>= 1) {
        pk[0] += __shfl_down_sync(0xffffffffu, pk[0], off);
        pk[1] += __shfl_down_sync(0xffffffffu, pk[1], off);
        pk[2] += __shfl_down_sync(0xffffffffu, pk[2], off);
    }
    if ((t & 31) == 0) {
        const int w = t >> 5;
        red[0][w] = pk[0];
        red[1][w] = pk[1];
        red[2][w] = pk[2];
    }
    __syncthreads();

    if (t == 0) {
        // single thread writes all 3 partials -> one fence orders them all
        #pragma unroll
        for (int k = 0; k < 3; ++k)
            g_part[(q * 3 + k) * NCHUNK + chunk] = red[k][0] + red[k][1];
        __threadfence();
        unsigned old = atomicAdd(&g_cnt[q], 1u);
        if (old == NCHUNK - 1u) {   // last CTA for this q: epilogue
            __threadfence();        // acquire: see other CTAs' g_part writes
            const float* r0 = aW1 + ((size_t)q * 3 + 0) * AGG_IN;
            const float* r1 = aW1 + ((size_t)q * 3 + 1) * AGG_IN;
            const float* r2 = aW1 + ((size_t)q * 3 + 2) * AGG_IN;
            float oh0 = __ldg(&r0[NN + l + 1]) + __ldg(&r0[NN + 4 + q]);
            float oh1 = __ldg(&r1[NN + l + 1]) + __ldg(&r1[NN + 4 + q]);
            float oh2 = __ldg(&r2[NN + l + 1]) + __ldg(&r2[NN + 4 + q]);
            float e10 = __ldg(&ab1[q * 3 + 0]);
            float e11 = __ldg(&ab1[q * 3 + 1]);
            float e12 = __ldg(&ab1[q * 3 + 2]);
            float w20 = __ldg(&aW2[q * 3 + 0]);
            float w21 = __ldg(&aW2[q * 3 + 1]);
            float w22 = __ldg(&aW2[q * 3 + 2]);
            float out = __ldg(&ab2[q]);

            const float* gp = &g_part[q * 3 * NCHUNK];
            float t0 = oh0 + e10, t1 = oh1 + e11, t2 = oh2 + e12;
            #pragma unroll
            for (int c = 0; c < NCHUNK; ++c) {
                t0 += gp[0 * NCHUNK + c];
                t1 += gp[1 * NCHUNK + c];
                t2 += gp[2 * NCHUNK + c];
            }
            out = fmaf(w20, tanh_e(t0), out);
            out = fmaf(w21, tanh_e(t1), out);
            out = fmaf(w22, tanh_e(t2), out);
            if (dout) dout[NN - 1 - q] = out;   // final layer: reversed
            else      g_act[out_buf][q] = out;
            g_cnt[q] = 0u;                      // reset for next layer / replay
        }
    }
}

extern "C" void kernel_launch(void* const* d_in, const int* in_sizes, int n_in,
                              void* d_out, int out_size)
{
    const float* x      = (const float*)d_in[0];
    const float* vec_W  = (const float*)d_in[1];
    const float* vec_b  = (const float*)d_in[2];
    const float* syn_W1 = (const float*)d_in[3];
    const float* syn_b1 = (const float*)d_in[4];
    const float* syn_W2 = (const float*)d_in[5];
    const float* syn_b2 = (const float*)d_in[6];
    const float* agg_W1 = (const float*)d_in[7];
    const float* agg_b1 = (const float*)d_in[8];
    const float* agg_W2 = (const float*)d_in[9];
    const float* agg_b2 = (const float*)d_in[10];
    float* out = (float*)d_out;

    const size_t VEC_L = (size_t)NN * NN * CC;
    const size_t SW1_L = (size_t)NN * NN * 48;
    const size_t SB1_L = (size_t)NN * NN * 3;
    const size_t SB2_L = (size_t)NN * NN;
    const size_t AW1_L = (size_t)NN * 3 * AGG_IN;
    const size_t AB1_L = (size_t)NN * 3;   // stride for agg_b1 AND agg_W2 (both (LT,N,3))
    const size_t AB2_L = (size_t)NN;       // stride for agg_b2 (LT,N)

    const int NCTA = (NN * NN) / EPC;   // 4096

    for (int l = 0; l < LTL; ++l) {
        const float* a_ext = (l == 0) ? x : nullptr;
        const int in_buf  = (l == 1) ? 0 : 1;
        const int out_buf = (l == 0) ? 0 : 1;
        float* dw = (l == LTL - 1) ? out : nullptr;

        edge_kernel<<<NCTA, TPB>>>(
            a_ext, in_buf, out_buf, l, dw,
            vec_W  + (size_t)l * VEC_L,  vec_b  + (size_t)l * VEC_L,
            syn_W1 + (size_t)l * SW1_L,  syn_b1 + (size_t)l * SB1_L,
            syn_W2 + (size_t)l * SB1_L,  syn_b2 + (size_t)l * SB2_L,
            agg_W1 + (size_t)l * AW1_L,  agg_b1 + (size_t)l * AB1_L,
            agg_W2 + (size_t)l * AB1_L,  agg_b2 + (size_t)l * AB2_L);
    }
}

// round 16
// speedup vs baseline: 1.1976x; 1.1976x over previous
#include <cuda_runtime.h>
#include <cstdint>

#define NN 512
#define CC 16
#define LTL 3
#define AGG_IN 1028
#define EPC 64             // edges per CTA
#define TPB 64
#define NCHUNK 8           // chunks per q

// scratch (no allocation allowed)
__device__ float g_part[NN * 3 * NCHUNK];  // per-(q,k,chunk) aggregator partials
__device__ unsigned g_cnt[NN];             // arrival counters (self-resetting)
__device__ float g_act[2][NN];             // ping-pong activations

__device__ __forceinline__ float tanh_e(float x) {
    x = fminf(fmaxf(x, -15.0f), 15.0f);
    float e = __expf(2.0f * x);
    return __fdividef(e - 1.0f, e + 1.0f);
}

__device__ __forceinline__ unsigned smem_u32(const void* p) {
    return (unsigned)__cvta_generic_to_shared(p);
}

__device__ __forceinline__ void mbar_init(unsigned mbar, unsigned count) {
    asm volatile("mbarrier.init.shared.b64 [%0], %1;" :: "r"(mbar), "r"(count) : "memory");
}
__device__ __forceinline__ void mbar_expect_tx(unsigned mbar, unsigned bytes) {
    asm volatile("mbarrier.arrive.expect_tx.shared.b64 _, [%0], %1;"
                 :: "r"(mbar), "r"(bytes) : "memory");
}
__device__ __forceinline__ void bulk_g2s(unsigned dst, const void* src,
                                         unsigned bytes, unsigned mbar) {
    asm volatile("cp.async.bulk.shared::cta.global.mbarrier::complete_tx::bytes "
                 "[%0], [%1], %2, [%3];"
                 :: "r"(dst), "l"(src), "r"(bytes), "r"(mbar) : "memory");
}
__device__ __forceinline__ void mbar_wait(unsigned mbar, unsigned parity) {
    asm volatile(
        "{\n\t"
        ".reg .pred P1;\n\t"
        "WAIT_LOOP_%=:\n\t"
        "mbarrier.try_wait.parity.acquire.cta.shared::cta.b64 P1, [%0], %1, 0x989680;\n\t"
        "@P1 bra.uni WAIT_DONE_%=;\n\t"
        "bra.uni WAIT_LOOP_%=;\n\t"
        "WAIT_DONE_%=:\n\t"
        "}"
        :: "r"(mbar), "r"(parity) : "memory");
}

// ---------------------------------------------------------------------------
// Edge kernel: cp.async.bulk (UBLKCP) staging + mbarrier, unpadded smem with
// phi-rotated conflict-free reads, split-wait overlap (VEC under sW1 fetch),
// fused aggregator partials + last-arriving-CTA epilogue (R13 lineage).
// Bulk engine depth is not scoreboard-bound -> more bytes in flight per SM.
// ---------------------------------------------------------------------------
__global__ __launch_bounds__(TPB, 16) void edge_kernel(
    const float* __restrict__ a_ext, int in_buf, int out_buf, int l,
    float* __restrict__ dout,
    const float* __restrict__ vW,  const float* __restrict__ vb,
    const float* __restrict__ sW1, const float* __restrict__ sb1,
    const float* __restrict__ sW2, const float* __restrict__ sb2,
    const float* __restrict__ aW1, const float* __restrict__ ab1,
    const float* __restrict__ aW2, const float* __restrict__ ab2)
{
    __shared__ float4 svW[EPC * 4];        // 4 KB, linear gmem image
    __shared__ float4 svb[EPC * 4];        // 4 KB
    __shared__ float4 sw1[EPC * 12];       // 12 KB
    __shared__ float red[3][2];
    __shared__ __align__(8) unsigned long long mbar[2];   // A: vW+vb, B: sW1

    const int t   = threadIdx.x;
    const int cta = blockIdx.x;
    const size_t e0 = (size_t)cta * EPC;
    const int q     = cta >> 3;
    const int chunk = cta & 7;
    const int p     = (chunk << 6) + t;
    const size_t eg = e0 + t;

    const unsigned mA = smem_u32(&mbar[0]);
    const unsigned mB = smem_u32(&mbar[1]);

    if (t == 0) {
        mbar_init(mA, 1);
        mbar_init(mB, 1);
    }
    __syncthreads();

    if (t == 0) {
        // group A: vW + vb (8 KB) -> barrier A
        mbar_expect_tx(mA, 2 * EPC * CC * 4);
        bulk_g2s(smem_u32(svW), vW + e0 * CC, EPC * CC * 4, mA);
        bulk_g2s(smem_u32(svb), vb + e0 * CC, EPC * CC * 4, mA);
        // group B: sW1 (12 KB) -> barrier B
        mbar_expect_tx(mB, EPC * 48 * 4);
        bulk_g2s(smem_u32(sw1), sW1 + e0 * 48, EPC * 48 * 4, mB);
    }

    // --- small direct loads (overlap with bulk transfers) ---
    const float* a_in = a_ext ? a_ext : g_act[in_buf];
    const float ap = __ldg(&a_in[p]);
    const float b1_0 = __ldg(&sb1[eg * 3 + 0]);
    const float b1_1 = __ldg(&sb1[eg * 3 + 1]);
    const float b1_2 = __ldg(&sb1[eg * 3 + 2]);
    const float w2_0 = __ldg(&sW2[eg * 3 + 0]);
    const float w2_1 = __ldg(&sW2[eg * 3 + 1]);
    const float w2_2 = __ldg(&sW2[eg * 3 + 2]);
    const float b2   = __ldg(&sb2[eg]);
    float aw[3];
    #pragma unroll
    for (int k = 0; k < 3; ++k)
        aw[k] = __ldg(&aW1[((size_t)q * 3 + k) * AGG_IN + p]);

    // phi-rotation: at step j read granule g=(j+phi)&3. Across the 8 lanes of
    // an LDS.128 phase, banks = (4t + g) mod 8 = {0|4} + {0,1,2,3} -> all 8
    // distinct -> conflict-free on the UNPADDED layout. f is indexed by j;
    // vW and sW1 use the same g(j), and the dot product is order-invariant.
    const int phi = (t >> 1) & 3;

    // --- wait for group A only; B (sW1) still streaming ---
    mbar_wait(mA, 0);

    // --- VEC: f[j-block] = tanh(ap*vW[g(j)] + vb[g(j)]) --- (overlaps B)
    float f[16];
    #pragma unroll
    for (int j = 0; j < 4; ++j) {
        const int g = (j + phi) & 3;
        float4 w = svW[t * 4 + g];
        float4 b = svb[t * 4 + g];
        f[4*j+0] = tanh_e(fmaf(ap, w.x, b.x));
        f[4*j+1] = tanh_e(fmaf(ap, w.y, b.y));
        f[4*j+2] = tanh_e(fmaf(ap, w.z, b.z));
        f[4*j+3] = tanh_e(fmaf(ap, w.w, b.w));
    }

    // --- now require sW1 ---
    mbar_wait(mB, 0);

    // --- Synapse: Linear(16->3) -> tanh -> Linear(3->1) -> tanh ---
    float h1[3];
    const float bb1[3] = {b1_0, b1_1, b1_2};
    #pragma unroll
    for (int o = 0; o < 3; ++o) {
        float acc = bb1[o];
        #pragma unroll
        for (int j = 0; j < 4; ++j) {
            const int g = (j + phi) & 3;
            float4 w = sw1[t * 12 + o * 4 + g];
            acc = fmaf(w.x, f[4*j+0], acc);
            acc = fmaf(w.y, f[4*j+1], acc);
            acc = fmaf(w.z, f[4*j+2], acc);
            acc = fmaf(w.w, f[4*j+3], acc);
        }
        h1[o] = tanh_e(acc);
    }
    float sv = b2;
    sv = fmaf(w2_0, h1[0], sv);
    sv = fmaf(w2_1, h1[1], sv);
    sv = fmaf(w2_2, h1[2], sv);
    const float s = tanh_e(sv);

    // --- fused aggregator partials: sum_p aW1[q,k,p]*s_p over this chunk ---
    float pk[3] = {aw[0] * s, aw[1] * s, aw[2] * s};
    #pragma unroll
    for (int off = 16; off > 0; off >>= 1) {
        pk[0] += __shfl_down_sync(0xffffffffu, pk[0], off);
        pk[1] += __shfl_down_sync(0xffffffffu, pk[1], off);
        pk[2] += __shfl_down_sync(0xffffffffu, pk[2], off);
    }
    if ((t & 31) == 0) {
        const int w = t >> 5;
        red[0][w] = pk[0];
        red[1][w] = pk[1];
        red[2][w] = pk[2];
    }
    __syncthreads();

    if (t == 0) {
        // single thread writes all 3 partials -> one fence orders them all
        #pragma unroll
        for (int k = 0; k < 3; ++k)
            g_part[(q * 3 + k) * NCHUNK + chunk] = red[k][0] + red[k][1];
        __threadfence();
        unsigned old = atomicAdd(&g_cnt[q], 1u);
        if (old == NCHUNK - 1u) {   // last CTA for this q: epilogue
            __threadfence();        // acquire: see other CTAs' g_part writes
            const float* r0 = aW1 + ((size_t)q * 3 + 0) * AGG_IN;
            const float* r1 = aW1 + ((size_t)q * 3 + 1) * AGG_IN;
            const float* r2 = aW1 + ((size_t)q * 3 + 2) * AGG_IN;
            float oh0 = __ldg(&r0[NN + l + 1]) + __ldg(&r0[NN + 4 + q]);
            float oh1 = __ldg(&r1[NN + l + 1]) + __ldg(&r1[NN + 4 + q]);
            float oh2 = __ldg(&r2[NN + l + 1]) + __ldg(&r2[NN + 4 + q]);
            float e10 = __ldg(&ab1[q * 3 + 0]);
            float e11 = __ldg(&ab1[q * 3 + 1]);
            float e12 = __ldg(&ab1[q * 3 + 2]);
            float w20 = __ldg(&aW2[q * 3 + 0]);
            float w21 = __ldg(&aW2[q * 3 + 1]);
            float w22 = __ldg(&aW2[q * 3 + 2]);
            float out = __ldg(&ab2[q]);

            const float* gp = &g_part[q * 3 * NCHUNK];
            float t0 = oh0 + e10, t1 = oh1 + e11, t2 = oh2 + e12;
            #pragma unroll
            for (int c = 0; c < NCHUNK; ++c) {
                t0 += gp[0 * NCHUNK + c];
                t1 += gp[1 * NCHUNK + c];
                t2 += gp[2 * NCHUNK + c];
            }
            out = fmaf(w20, tanh_e(t0), out);
            out = fmaf(w21, tanh_e(t1), out);
            out = fmaf(w22, tanh_e(t2), out);
            if (dout) dout[NN - 1 - q] = out;   // final layer: reversed
            else      g_act[out_buf][q] = out;
            g_cnt[q] = 0u;                      // reset for next layer / replay
        }
    }
}

extern "C" void kernel_launch(void* const* d_in, const int* in_sizes, int n_in,
                              void* d_out, int out_size)
{
    const float* x      = (const float*)d_in[0];
    const float* vec_W  = (const float*)d_in[1];
    const float* vec_b  = (const float*)d_in[2];
    const float* syn_W1 = (const float*)d_in[3];
    const float* syn_b1 = (const float*)d_in[4];
    const float* syn_W2 = (const float*)d_in[5];
    const float* syn_b2 = (const float*)d_in[6];
    const float* agg_W1 = (const float*)d_in[7];
    const float* agg_b1 = (const float*)d_in[8];
    const float* agg_W2 = (const float*)d_in[9];
    const float* agg_b2 = (const float*)d_in[10];
    float* out = (float*)d_out;

    const size_t VEC_L = (size_t)NN * NN * CC;
    const size_t SW1_L = (size_t)NN * NN * 48;
    const size_t SB1_L = (size_t)NN * NN * 3;
    const size_t SB2_L = (size_t)NN * NN;
    const size_t AW1_L = (size_t)NN * 3 * AGG_IN;
    const size_t AB1_L = (size_t)NN * 3;   // stride for agg_b1 AND agg_W2 (both (LT,N,3))
    const size_t AB2_L = (size_t)NN;       // stride for agg_b2 (LT,N)

    const int NCTA = (NN * NN) / EPC;   // 4096

    for (int l = 0; l < LTL; ++l) {
        const float* a_ext = (l == 0) ? x : nullptr;
        const int in_buf  = (l == 1) ? 0 : 1;
        const int out_buf = (l == 0) ? 0 : 1;
        float* dw = (l == LTL - 1) ? out : nullptr;

        edge_kernel<<<NCTA, TPB>>>(
            a_ext, in_buf, out_buf, l, dw,
            vec_W  + (size_t)l * VEC_L,  vec_b  + (size_t)l * VEC_L,
            syn_W1 + (size_t)l * SW1_L,  syn_b1 + (size_t)l * SB1_L,
            syn_W2 + (size_t)l * SB1_L,  syn_b2 + (size_t)l * SB2_L,
            agg_W1 + (size_t)l * AW1_L,  agg_b1 + (size_t)l * AB1_L,
            agg_W2 + (size_t)l * AB1_L,  agg_b2 + (size_t)l * AB2_L);
    }
}